// round 1
// baseline (speedup 1.0000x reference)
#include <cuda_runtime.h>
#include <math.h>

// ---------------------------------------------------------------------------
// AttentionFusion: 3-modality projection + LN/ReLU, 3-token 8-head MHA,
// gated fusion, classifier head.  B=16384, E=512, H=8, HD=64, NC=6.
// Round 0: fp32 SGEMM baseline (tensor cores come next).
// ---------------------------------------------------------------------------

#define BATCH 16384

// scratch (device globals -- allocation-free kernel_launch requirement)
__device__ float g_proj [BATCH * 1536];   // (B,3,512) == (B,1536) concat
__device__ float g_qkv  [BATCH * 4608];   // (B,3,1536)
__device__ float g_ctx  [BATCH * 1536];   // (B,3,512)
__device__ float g_att  [BATCH * 1536];   // (B,3,512)
__device__ float g_gh   [BATCH * 512];    // gate hidden
__device__ float g_fused[BATCH * 512];
__device__ float g_chid [BATCH * 256];    // classifier hidden (pre-LN)

__device__ __forceinline__ float warpSum(float v) {
#pragma unroll
    for (int o = 16; o > 0; o >>= 1) v += __shfl_xor_sync(0xffffffffu, v, o);
    return v;
}

// 128-thread block sum; sred must be __shared__ float[4]; safe to call repeatedly
__device__ __forceinline__ float blockSum128(float v, float* sred) {
    int lane = threadIdx.x & 31, w = threadIdx.x >> 5;
    v = warpSum(v);
    __syncthreads();               // protect sred reuse across calls
    if (lane == 0) sred[w] = v;
    __syncthreads();
    return sred[0] + sred[1] + sred[2] + sred[3];
}

// ---------------------------------------------------------------------------
// SGEMM: C[M,N] = A[M,K] * W[N,K]^T + bias   (torch Linear layout)
// BM=BN=128, BK=8, 256 threads, 8x8 per-thread microtile.
// Requires M%128==0, N%128==0, K%8==0 (all shapes here satisfy this).
// ---------------------------------------------------------------------------
template<int RELU>
__global__ void __launch_bounds__(256, 2) sgemm_nt(
    const float* __restrict__ A, const float* __restrict__ W,
    const float* __restrict__ bias, float* __restrict__ C,
    int K, int ldc)
{
    __shared__ float As[8][128];
    __shared__ float Ws[8][128];
    const int bm = blockIdx.y << 7;
    const int bn = blockIdx.x << 7;
    const int tid = threadIdx.x;
    const int lr = tid >> 1;          // 0..127 : row within tile for loads
    const int lc = (tid & 1) << 2;    // 0 or 4 : k offset for float4 load
    const float* Ap = A + (size_t)(bm + lr) * K + lc;
    const float* Wp = W + (size_t)(bn + lr) * K + lc;
    const int tm = (tid >> 4) << 3;   // 0..120
    const int tn = (tid & 15) << 3;   // 0..120

    float acc[8][8];
#pragma unroll
    for (int i = 0; i < 8; i++)
#pragma unroll
        for (int j = 0; j < 8; j++) acc[i][j] = 0.f;

    for (int k0 = 0; k0 < K; k0 += 8) {
        float4 a = *reinterpret_cast<const float4*>(Ap + k0);
        float4 w = *reinterpret_cast<const float4*>(Wp + k0);
        As[lc + 0][lr] = a.x; As[lc + 1][lr] = a.y;
        As[lc + 2][lr] = a.z; As[lc + 3][lr] = a.w;
        Ws[lc + 0][lr] = w.x; Ws[lc + 1][lr] = w.y;
        Ws[lc + 2][lr] = w.z; Ws[lc + 3][lr] = w.w;
        __syncthreads();
#pragma unroll
        for (int kk = 0; kk < 8; kk++) {
            float ra[8], rw[8];
#pragma unroll
            for (int i = 0; i < 8; i++) ra[i] = As[kk][tm + i];
#pragma unroll
            for (int j = 0; j < 8; j++) rw[j] = Ws[kk][tn + j];
#pragma unroll
            for (int i = 0; i < 8; i++)
#pragma unroll
                for (int j = 0; j < 8; j++)
                    acc[i][j] = fmaf(ra[i], rw[j], acc[i][j]);
        }
        __syncthreads();
    }

    float bv[8];
#pragma unroll
    for (int j = 0; j < 8; j++) bv[j] = bias[bn + tn + j];
#pragma unroll
    for (int i = 0; i < 8; i++) {
        float* Cp = C + (size_t)(bm + tm + i) * ldc + bn + tn;
#pragma unroll
        for (int j = 0; j < 8; j++) {
            float v = acc[i][j] + bv[j];
            if (RELU) v = fmaxf(v, 0.f);
            Cp[j] = v;
        }
    }
}

// ---------------------------------------------------------------------------
// In-place LayerNorm + ReLU over 512-wide rows; modality = row % 3 picks g/beta
// ---------------------------------------------------------------------------
__global__ void __launch_bounds__(128) ln_relu3(
    float* __restrict__ x,
    const float* __restrict__ g0, const float* __restrict__ be0,
    const float* __restrict__ g1, const float* __restrict__ be1,
    const float* __restrict__ g2, const float* __restrict__ be2)
{
    __shared__ float sred[4];
    int row = blockIdx.x;
    int s = row % 3;
    const float* g  = (s == 0) ? g0 : (s == 1) ? g1 : g2;
    const float* be = (s == 0) ? be0 : (s == 1) ? be1 : be2;
    float4* xr = reinterpret_cast<float4*>(x + (size_t)row * 512);
    int t = threadIdx.x;
    float4 v = xr[t];
    float sum = blockSum128(v.x + v.y + v.z + v.w, sred);
    float mean = sum * (1.f / 512.f);
    float dx = v.x - mean, dy = v.y - mean, dz = v.z - mean, dw = v.w - mean;
    float ss = blockSum128(dx * dx + dy * dy + dz * dz + dw * dw, sred);
    float rstd = rsqrtf(ss * (1.f / 512.f) + 1e-5f);
    float4 gv = reinterpret_cast<const float4*>(g)[t];
    float4 bv = reinterpret_cast<const float4*>(be)[t];
    float4 o;
    o.x = fmaxf(dx * rstd * gv.x + bv.x, 0.f);
    o.y = fmaxf(dy * rstd * gv.y + bv.y, 0.f);
    o.z = fmaxf(dz * rstd * gv.z + bv.z, 0.f);
    o.w = fmaxf(dw * rstd * gv.w + bv.w, 0.f);
    xr[t] = o;
}

// ---------------------------------------------------------------------------
// 3-token, 8-head attention.  One warp per (sample, head).
// qkv row layout per token: [q(512) | k(512) | v(512)], head h at h*64.
// ---------------------------------------------------------------------------
__global__ void __launch_bounds__(128) attn3(
    const float* __restrict__ qkv, float* __restrict__ ctx)
{
    int warp = blockIdx.x * 4 + (threadIdx.x >> 5);
    int lane = threadIdx.x & 31;
    int b = warp >> 3, h = warp & 7;
    const float* base = qkv + (size_t)b * 4608 + h * 64 + 2 * lane;
    float2 q[3], k[3], v[3];
#pragma unroll
    for (int t = 0; t < 3; t++) {
        q[t] = *reinterpret_cast<const float2*>(base + t * 1536);
        k[t] = *reinterpret_cast<const float2*>(base + t * 1536 + 512);
        v[t] = *reinterpret_cast<const float2*>(base + t * 1536 + 1024);
    }
    float a[3][3];
#pragma unroll
    for (int i = 0; i < 3; i++)
#pragma unroll
        for (int j = 0; j < 3; j++) {
            float p = q[i].x * k[j].x + q[i].y * k[j].y;
            a[i][j] = warpSum(p) * 0.125f;   // 1/sqrt(64)
        }
#pragma unroll
    for (int i = 0; i < 3; i++) {
        float m = fmaxf(a[i][0], fmaxf(a[i][1], a[i][2]));
        float e0 = expf(a[i][0] - m), e1 = expf(a[i][1] - m), e2 = expf(a[i][2] - m);
        float inv = 1.f / (e0 + e1 + e2);
        a[i][0] = e0 * inv; a[i][1] = e1 * inv; a[i][2] = e2 * inv;
    }
#pragma unroll
    for (int i = 0; i < 3; i++) {
        float2 o;
        o.x = a[i][0] * v[0].x + a[i][1] * v[1].x + a[i][2] * v[2].x;
        o.y = a[i][0] * v[0].y + a[i][1] * v[1].y + a[i][2] * v[2].y;
        *reinterpret_cast<float2*>(ctx + (size_t)(b * 3 + i) * 512 + h * 64 + 2 * lane) = o;
    }
}

// ---------------------------------------------------------------------------
// Gate logits (3 dots of 512) + softmax + weighted sum of attended tokens.
// One 128-thread block per sample.
// ---------------------------------------------------------------------------
__global__ void __launch_bounds__(128) gate_fuse(
    const float* __restrict__ gh, const float* __restrict__ gw2,
    const float* __restrict__ gb2, const float* __restrict__ att,
    float* __restrict__ fused, float* __restrict__ gate_out)
{
    __shared__ float sred[4];
    int b = blockIdx.x, t = threadIdx.x;
    float4 hv = reinterpret_cast<const float4*>(gh + (size_t)b * 512)[t];
    float l[3];
#pragma unroll
    for (int s = 0; s < 3; s++) {
        float4 w = reinterpret_cast<const float4*>(gw2 + s * 512)[t];
        l[s] = blockSum128(hv.x * w.x + hv.y * w.y + hv.z * w.z + hv.w * w.w, sred)
             + gb2[s];
    }
    float m = fmaxf(l[0], fmaxf(l[1], l[2]));
    float e0 = expf(l[0] - m), e1 = expf(l[1] - m), e2 = expf(l[2] - m);
    float inv = 1.f / (e0 + e1 + e2);
    float w0 = e0 * inv, w1 = e1 * inv, w2 = e2 * inv;
    if (t == 0) {
        gate_out[b * 3 + 0] = w0;
        gate_out[b * 3 + 1] = w1;
        gate_out[b * 3 + 2] = w2;
    }
    const float4* ar = reinterpret_cast<const float4*>(att + (size_t)b * 1536);
    float4 x0 = ar[t], x1 = ar[128 + t], x2 = ar[256 + t];
    float4 o;
    o.x = w0 * x0.x + w1 * x1.x + w2 * x2.x;
    o.y = w0 * x0.y + w1 * x1.y + w2 * x2.y;
    o.z = w0 * x0.z + w1 * x1.z + w2 * x2.z;
    o.w = w0 * x0.w + w1 * x1.w + w2 * x2.w;
    reinterpret_cast<float4*>(fused + (size_t)b * 512)[t] = o;
}

// ---------------------------------------------------------------------------
// Classifier head: LN(256) + ReLU + 6-way linear.  One warp per sample.
// ---------------------------------------------------------------------------
__global__ void __launch_bounds__(128) cls_head(
    const float* __restrict__ chid, const float* __restrict__ cg,
    const float* __restrict__ cbeta, const float* __restrict__ cw2,
    const float* __restrict__ cb2, float* __restrict__ logits)
{
    int b = blockIdx.x * 4 + (threadIdx.x >> 5);
    int lane = threadIdx.x & 31;
    const float* hr = chid + (size_t)b * 256;
    float4 h0 = reinterpret_cast<const float4*>(hr)[lane];
    float4 h1 = reinterpret_cast<const float4*>(hr)[lane + 32];
    float sum = warpSum(h0.x + h0.y + h0.z + h0.w + h1.x + h1.y + h1.z + h1.w);
    float mean = sum * (1.f / 256.f);
    h0.x -= mean; h0.y -= mean; h0.z -= mean; h0.w -= mean;
    h1.x -= mean; h1.y -= mean; h1.z -= mean; h1.w -= mean;
    float ss = warpSum(h0.x * h0.x + h0.y * h0.y + h0.z * h0.z + h0.w * h0.w
                     + h1.x * h1.x + h1.y * h1.y + h1.z * h1.z + h1.w * h1.w);
    float rstd = rsqrtf(ss * (1.f / 256.f) + 1e-5f);
    float4 cg0 = reinterpret_cast<const float4*>(cg)[lane];
    float4 cg1 = reinterpret_cast<const float4*>(cg)[lane + 32];
    float4 cb0 = reinterpret_cast<const float4*>(cbeta)[lane];
    float4 cb1 = reinterpret_cast<const float4*>(cbeta)[lane + 32];
    h0.x = fmaxf(h0.x * rstd * cg0.x + cb0.x, 0.f);
    h0.y = fmaxf(h0.y * rstd * cg0.y + cb0.y, 0.f);
    h0.z = fmaxf(h0.z * rstd * cg0.z + cb0.z, 0.f);
    h0.w = fmaxf(h0.w * rstd * cg0.w + cb0.w, 0.f);
    h1.x = fmaxf(h1.x * rstd * cg1.x + cb1.x, 0.f);
    h1.y = fmaxf(h1.y * rstd * cg1.y + cb1.y, 0.f);
    h1.z = fmaxf(h1.z * rstd * cg1.z + cb1.z, 0.f);
    h1.w = fmaxf(h1.w * rstd * cg1.w + cb1.w, 0.f);
#pragma unroll
    for (int c = 0; c < 6; c++) {
        const float4* wr = reinterpret_cast<const float4*>(cw2 + c * 256);
        float4 w0 = wr[lane], w1 = wr[lane + 32];
        float p = h0.x * w0.x + h0.y * w0.y + h0.z * w0.z + h0.w * w0.w
                + h1.x * w1.x + h1.y * w1.y + h1.z * w1.z + h1.w * w1.w;
        p = warpSum(p);
        if (lane == 0) logits[(size_t)b * 6 + c] = p + cb2[c];
    }
}

// ---------------------------------------------------------------------------
extern "C" void kernel_launch(void* const* d_in, const int* in_sizes, int n_in,
                              void* d_out, int out_size)
{
    const float* rgb       = (const float*)d_in[0];
    const float* pose      = (const float*)d_in[1];
    const float* flow      = (const float*)d_in[2];
    const float* rgb_w     = (const float*)d_in[3];
    const float* rgb_b     = (const float*)d_in[4];
    const float* rgb_g     = (const float*)d_in[5];
    const float* rgb_beta  = (const float*)d_in[6];
    const float* pose_w    = (const float*)d_in[7];
    const float* pose_b    = (const float*)d_in[8];
    const float* pose_g    = (const float*)d_in[9];
    const float* pose_beta = (const float*)d_in[10];
    const float* flow_w    = (const float*)d_in[11];
    const float* flow_b    = (const float*)d_in[12];
    const float* flow_g    = (const float*)d_in[13];
    const float* flow_beta = (const float*)d_in[14];
    const float* in_w      = (const float*)d_in[15];
    const float* in_b      = (const float*)d_in[16];
    const float* out_w     = (const float*)d_in[17];
    const float* out_b     = (const float*)d_in[18];
    const float* gw1       = (const float*)d_in[19];
    const float* gb1       = (const float*)d_in[20];
    const float* gw2       = (const float*)d_in[21];
    const float* gb2       = (const float*)d_in[22];
    const float* cw1       = (const float*)d_in[23];
    const float* cb1       = (const float*)d_in[24];
    const float* cg        = (const float*)d_in[25];
    const float* cbeta     = (const float*)d_in[26];
    const float* cw2       = (const float*)d_in[27];
    const float* cb2       = (const float*)d_in[28];

    float* out = (float*)d_out;                 // [B*6 logits | B*3 gate]
    float* logits_out = out;
    float* gate_out   = out + (size_t)BATCH * 6;

    float *proj, *qkv, *ctx, *att, *gh, *fused, *chid;
    cudaGetSymbolAddress((void**)&proj,  g_proj);
    cudaGetSymbolAddress((void**)&qkv,   g_qkv);
    cudaGetSymbolAddress((void**)&ctx,   g_ctx);
    cudaGetSymbolAddress((void**)&att,   g_att);
    cudaGetSymbolAddress((void**)&gh,    g_gh);
    cudaGetSymbolAddress((void**)&fused, g_fused);
    cudaGetSymbolAddress((void**)&chid,  g_chid);

    // 1) per-modality projections -> stacked/concat buffer (B,3,512)
    sgemm_nt<0><<<dim3(4, 128), 256>>>(rgb,  rgb_w,  rgb_b,  proj + 0,    768,  1536);
    sgemm_nt<0><<<dim3(4, 128), 256>>>(pose, pose_w, pose_b, proj + 512,  640,  1536);
    sgemm_nt<0><<<dim3(4, 128), 256>>>(flow, flow_w, flow_b, proj + 1024, 1024, 1536);
    // 2) LN + ReLU per (b, modality) row
    ln_relu3<<<BATCH * 3, 128>>>(proj, rgb_g, rgb_beta, pose_g, pose_beta,
                                 flow_g, flow_beta);
    // 3) packed QKV projection (49152 x 512) x (1536 x 512)^T
    sgemm_nt<0><<<dim3(12, 384), 256>>>(proj, in_w, in_b, qkv, 512, 1536);
    // 4) 3-token 8-head attention
    attn3<<<BATCH * 8 / 4, 128>>>(qkv, ctx);
    // 5) attention out-projection
    sgemm_nt<0><<<dim3(4, 384), 256>>>(ctx, out_w, out_b, att, 512, 512);
    // 6) gate MLP layer 1 (uses proj as (B,1536) concat) with ReLU
    sgemm_nt<1><<<dim3(4, 128), 256>>>(proj, gw1, gb1, gh, 1536, 512);
    // 7) gate logits + softmax + weighted fusion (also writes gate output)
    gate_fuse<<<BATCH, 128>>>(gh, gw2, gb2, att, fused, gate_out);
    // 8) classifier layer 1
    sgemm_nt<0><<<dim3(2, 128), 256>>>(fused, cw1, cb1, chid, 512, 256);
    // 9) LN + ReLU + 6-way head
    cls_head<<<BATCH / 4, 128>>>(chid, cg, cbeta, cw2, cb2, logits_out);
}

// round 3
// speedup vs baseline: 2.6167x; 2.6167x over previous
#include <cuda_runtime.h>
#include <cstdint>
#include <math.h>

// ---------------------------------------------------------------------------
// AttentionFusion on GB300 (sm_103): tf32 mma.sync GEMMs + fused elementwise.
// B=16384, E=512, H=8, HD=64, NC=6.
// NOTE: harness PTX targets compute_103 (no 'a'), so tcgen05 is unavailable;
// sm_80-style mma.sync tf32 is the tensor-core path that compiles here.
// ---------------------------------------------------------------------------

#define BATCH 16384

// scratch (device globals -- allocation-free kernel_launch requirement)
__device__ float g_proj [BATCH * 1536];   // (B,3,512) == (B,1536) concat
__device__ float g_qkv  [BATCH * 4608];   // (B,3,1536)
__device__ float g_ctx  [BATCH * 1536];   // (B,3,512)
__device__ float g_att  [BATCH * 1536];   // (B,3,512)
__device__ float g_gh   [BATCH * 512];    // gate hidden
__device__ float g_fused[BATCH * 512];
__device__ float g_chid [BATCH * 256];    // classifier hidden (pre-LN)

__device__ __forceinline__ uint32_t smem_u32(const void* p) {
    uint32_t a;
    asm("{ .reg .u64 t; cvta.to.shared.u64 t, %1; cvt.u32.u64 %0, t; }"
        : "=r"(a) : "l"(p));
    return a;
}

// ---------------------------------------------------------------------------
// tf32 tensor-core GEMM: C[M,N] = A[M,K] * W[N,K]^T + bias  (torch Linear)
// BM=BN=128, BK=32, 256 threads = 8 warps (4 m x 2 n), warp tile 32x64.
// 3-stage cp.async pipeline.  Smem rows padded to 36 floats -> fragment
// LDS bank = (m*36+k)%32 == lane  => conflict-free.
// RNA tf32 rounding via bits+0x1000 (hw truncates low 13 bits afterwards).
// Requires M%128==0, N%128==0, K%32==0.
// ---------------------------------------------------------------------------
constexpr int T_BM = 128, T_BN = 128, T_BK = 32;
constexpr int T_STAGES = 3;
constexpr int T_ROWW = 36;                               // floats per padded row
constexpr int T_STAGEF = 2 * 128 * T_ROWW;               // floats per stage (A+B)
constexpr int T_SMEM = T_STAGES * T_STAGEF * 4;          // 110592 bytes

template<int RELU>
__global__ void __launch_bounds__(256, 1) gemm_tc(
    const float* __restrict__ A, const float* __restrict__ W,
    const float* __restrict__ bias, float* __restrict__ C,
    int K, int ldc)
{
    extern __shared__ __align__(16) float smem[];
    const int tid  = threadIdx.x;
    const int wid  = tid >> 5, lane = tid & 31;
    const int q    = lane >> 2;          // 0..7
    const int kr   = lane & 3;           // 0..3
    const int wm   = wid & 3;            // warp m index (0..3) -> 32 rows
    const int wn   = wid >> 2;           // warp n index (0..1) -> 64 cols
    const int bm   = blockIdx.y * T_BM;
    const int bn   = blockIdx.x * T_BN;

    // ------- cp.async source/dest mapping: thread covers 4 segs of A + 4 of B
    const int lrow = tid >> 1;                 // 0..127
    const int s0   = (tid & 1) * 4;            // seg base (segs are 16B)
    const float* Arow = A + (size_t)(bm + lrow) * K;
    const float* Wrow = W + (size_t)(bn + lrow) * K;
    uint32_t sA[T_STAGES], sB[T_STAGES];
#pragma unroll
    for (int s = 0; s < T_STAGES; s++) {
        sA[s] = smem_u32(smem + s * T_STAGEF + lrow * T_ROWW + s0 * 4);
        sB[s] = smem_u32(smem + s * T_STAGEF + 128 * T_ROWW + lrow * T_ROWW + s0 * 4);
    }

#define LOAD_CHUNK(kc_) do {                                                  \
        const int st_ = (kc_) % T_STAGES;                                     \
        const float* ap_ = Arow + (kc_) * T_BK + s0 * 4;                      \
        const float* wp_ = Wrow + (kc_) * T_BK + s0 * 4;                      \
        _Pragma("unroll")                                                     \
        for (int i = 0; i < 4; i++)                                           \
            asm volatile("cp.async.cg.shared.global [%0], [%1], 16;"          \
                :: "r"(sA[st_] + i * 16), "l"(ap_ + i * 4) : "memory");       \
        _Pragma("unroll")                                                     \
        for (int i = 0; i < 4; i++)                                           \
            asm volatile("cp.async.cg.shared.global [%0], [%1], 16;"          \
                :: "r"(sB[st_] + i * 16), "l"(wp_ + i * 4) : "memory");       \
        asm volatile("cp.async.commit_group;" ::: "memory");                  \
    } while (0)

    const int KC = K / T_BK;

    // prologue: fill pipeline
    LOAD_CHUNK(0); LOAD_CHUNK(1); LOAD_CHUNK(2);

    float c[2][8][4];
#pragma unroll
    for (int t = 0; t < 2; t++)
#pragma unroll
        for (int j = 0; j < 8; j++)
#pragma unroll
            for (int r = 0; r < 4; r++) c[t][j][r] = 0.f;

    const int mb = wm * 32;     // within-tile warp row base
    const int nb = wn * 64;     // within-tile warp col base

    for (int kc = 0; kc < KC; kc++) {
        asm volatile("cp.async.wait_group 2;" ::: "memory");
        __syncthreads();
        const float* As = smem + (kc % T_STAGES) * T_STAGEF;
        const float* Bs = As + 128 * T_ROWW;
#pragma unroll
        for (int ks = 0; ks < 4; ks++) {
            const int ka = ks * 8 + kr;
            uint32_t a[2][4], b[8][2];
#pragma unroll
            for (int t = 0; t < 2; t++) {
                const int r0 = mb + t * 16 + q;
                a[t][0] = __float_as_uint(As[(r0)     * T_ROWW + ka])     + 0x1000u;
                a[t][1] = __float_as_uint(As[(r0 + 8) * T_ROWW + ka])     + 0x1000u;
                a[t][2] = __float_as_uint(As[(r0)     * T_ROWW + ka + 4]) + 0x1000u;
                a[t][3] = __float_as_uint(As[(r0 + 8) * T_ROWW + ka + 4]) + 0x1000u;
            }
#pragma unroll
            for (int j = 0; j < 8; j++) {
                const int n0 = nb + j * 8 + q;
                b[j][0] = __float_as_uint(Bs[n0 * T_ROWW + ka])     + 0x1000u;
                b[j][1] = __float_as_uint(Bs[n0 * T_ROWW + ka + 4]) + 0x1000u;
            }
#pragma unroll
            for (int t = 0; t < 2; t++)
#pragma unroll
                for (int j = 0; j < 8; j++)
                    asm volatile(
                        "mma.sync.aligned.m16n8k8.row.col.f32.tf32.tf32.f32 "
                        "{%0,%1,%2,%3}, {%4,%5,%6,%7}, {%8,%9}, {%0,%1,%2,%3};"
                        : "+f"(c[t][j][0]), "+f"(c[t][j][1]),
                          "+f"(c[t][j][2]), "+f"(c[t][j][3])
                        : "r"(a[t][0]), "r"(a[t][1]), "r"(a[t][2]), "r"(a[t][3]),
                          "r"(b[j][0]), "r"(b[j][1]));
        }
        __syncthreads();
        const int kn = kc + T_STAGES;
        if (kn < KC) { LOAD_CHUNK(kn); }
        else asm volatile("cp.async.commit_group;" ::: "memory");
    }
#undef LOAD_CHUNK

    // epilogue: bias (+ReLU), float2 stores
#pragma unroll
    for (int t = 0; t < 2; t++) {
        const int r0 = bm + mb + t * 16 + q;
#pragma unroll
        for (int j = 0; j < 8; j++) {
            const int col = bn + nb + j * 8 + (kr << 1);
            const float b0 = bias[col], b1 = bias[col + 1];
            float2 v0, v1;
            v0.x = c[t][j][0] + b0; v0.y = c[t][j][1] + b1;
            v1.x = c[t][j][2] + b0; v1.y = c[t][j][3] + b1;
            if (RELU) {
                v0.x = fmaxf(v0.x, 0.f); v0.y = fmaxf(v0.y, 0.f);
                v1.x = fmaxf(v1.x, 0.f); v1.y = fmaxf(v1.y, 0.f);
            }
            *reinterpret_cast<float2*>(C + (size_t)r0 * ldc + col)       = v0;
            *reinterpret_cast<float2*>(C + (size_t)(r0 + 8) * ldc + col) = v1;
        }
    }
}

// ---------------------------------------------------------------------------
// elementwise / small kernels
// ---------------------------------------------------------------------------
__device__ __forceinline__ float warpSum(float v) {
#pragma unroll
    for (int o = 16; o > 0; o >>= 1) v += __shfl_xor_sync(0xffffffffu, v, o);
    return v;
}

__device__ __forceinline__ float blockSum128(float v, float* sred) {
    int lane = threadIdx.x & 31, w = threadIdx.x >> 5;
    v = warpSum(v);
    __syncthreads();
    if (lane == 0) sred[w] = v;
    __syncthreads();
    return sred[0] + sred[1] + sred[2] + sred[3];
}

__global__ void __launch_bounds__(128) ln_relu3(
    float* __restrict__ x,
    const float* __restrict__ g0, const float* __restrict__ be0,
    const float* __restrict__ g1, const float* __restrict__ be1,
    const float* __restrict__ g2, const float* __restrict__ be2)
{
    __shared__ float sred[4];
    int row = blockIdx.x;
    int s = row % 3;
    const float* g  = (s == 0) ? g0 : (s == 1) ? g1 : g2;
    const float* be = (s == 0) ? be0 : (s == 1) ? be1 : be2;
    float4* xr = reinterpret_cast<float4*>(x + (size_t)row * 512);
    int t = threadIdx.x;
    float4 v = xr[t];
    float sum = blockSum128(v.x + v.y + v.z + v.w, sred);
    float mean = sum * (1.f / 512.f);
    float dx = v.x - mean, dy = v.y - mean, dz = v.z - mean, dw = v.w - mean;
    float ss = blockSum128(dx * dx + dy * dy + dz * dz + dw * dw, sred);
    float rstd = rsqrtf(ss * (1.f / 512.f) + 1e-5f);
    float4 gv = reinterpret_cast<const float4*>(g)[t];
    float4 bv = reinterpret_cast<const float4*>(be)[t];
    float4 o;
    o.x = fmaxf(dx * rstd * gv.x + bv.x, 0.f);
    o.y = fmaxf(dy * rstd * gv.y + bv.y, 0.f);
    o.z = fmaxf(dz * rstd * gv.z + bv.z, 0.f);
    o.w = fmaxf(dw * rstd * gv.w + bv.w, 0.f);
    xr[t] = o;
}

__global__ void __launch_bounds__(128) attn3(
    const float* __restrict__ qkv, float* __restrict__ ctx)
{
    int warp = blockIdx.x * 4 + (threadIdx.x >> 5);
    int lane = threadIdx.x & 31;
    int b = warp >> 3, h = warp & 7;
    const float* base = qkv + (size_t)b * 4608 + h * 64 + 2 * lane;
    float2 q[3], k[3], v[3];
#pragma unroll
    for (int t = 0; t < 3; t++) {
        q[t] = *reinterpret_cast<const float2*>(base + t * 1536);
        k[t] = *reinterpret_cast<const float2*>(base + t * 1536 + 512);
        v[t] = *reinterpret_cast<const float2*>(base + t * 1536 + 1024);
    }
    float a[3][3];
#pragma unroll
    for (int i = 0; i < 3; i++)
#pragma unroll
        for (int j = 0; j < 3; j++) {
            float p = q[i].x * k[j].x + q[i].y * k[j].y;
            a[i][j] = warpSum(p) * 0.125f;
        }
#pragma unroll
    for (int i = 0; i < 3; i++) {
        float m = fmaxf(a[i][0], fmaxf(a[i][1], a[i][2]));
        float e0 = expf(a[i][0] - m), e1 = expf(a[i][1] - m), e2 = expf(a[i][2] - m);
        float inv = 1.f / (e0 + e1 + e2);
        a[i][0] = e0 * inv; a[i][1] = e1 * inv; a[i][2] = e2 * inv;
    }
#pragma unroll
    for (int i = 0; i < 3; i++) {
        float2 o;
        o.x = a[i][0] * v[0].x + a[i][1] * v[1].x + a[i][2] * v[2].x;
        o.y = a[i][0] * v[0].y + a[i][1] * v[1].y + a[i][2] * v[2].y;
        *reinterpret_cast<float2*>(ctx + (size_t)(b * 3 + i) * 512 + h * 64 + 2 * lane) = o;
    }
}

__global__ void __launch_bounds__(128) gate_fuse(
    const float* __restrict__ gh, const float* __restrict__ gw2,
    const float* __restrict__ gb2, const float* __restrict__ att,
    float* __restrict__ fused, float* __restrict__ gate_out)
{
    __shared__ float sred[4];
    int b = blockIdx.x, t = threadIdx.x;
    float4 hv = reinterpret_cast<const float4*>(gh + (size_t)b * 512)[t];
    float l[3];
#pragma unroll
    for (int s = 0; s < 3; s++) {
        float4 w = reinterpret_cast<const float4*>(gw2 + s * 512)[t];
        l[s] = blockSum128(hv.x * w.x + hv.y * w.y + hv.z * w.z + hv.w * w.w, sred)
             + gb2[s];
    }
    float m = fmaxf(l[0], fmaxf(l[1], l[2]));
    float e0 = expf(l[0] - m), e1 = expf(l[1] - m), e2 = expf(l[2] - m);
    float inv = 1.f / (e0 + e1 + e2);
    float w0 = e0 * inv, w1 = e1 * inv, w2 = e2 * inv;
    if (t == 0) {
        gate_out[b * 3 + 0] = w0;
        gate_out[b * 3 + 1] = w1;
        gate_out[b * 3 + 2] = w2;
    }
    const float4* ar = reinterpret_cast<const float4*>(att + (size_t)b * 1536);
    float4 x0 = ar[t], x1 = ar[128 + t], x2 = ar[256 + t];
    float4 o;
    o.x = w0 * x0.x + w1 * x1.x + w2 * x2.x;
    o.y = w0 * x0.y + w1 * x1.y + w2 * x2.y;
    o.z = w0 * x0.z + w1 * x1.z + w2 * x2.z;
    o.w = w0 * x0.w + w1 * x1.w + w2 * x2.w;
    reinterpret_cast<float4*>(fused + (size_t)b * 512)[t] = o;
}

__global__ void __launch_bounds__(128) cls_head(
    const float* __restrict__ chid, const float* __restrict__ cg,
    const float* __restrict__ cbeta, const float* __restrict__ cw2,
    const float* __restrict__ cb2, float* __restrict__ logits)
{
    int b = blockIdx.x * 4 + (threadIdx.x >> 5);
    int lane = threadIdx.x & 31;
    const float* hr = chid + (size_t)b * 256;
    float4 h0 = reinterpret_cast<const float4*>(hr)[lane];
    float4 h1 = reinterpret_cast<const float4*>(hr)[lane + 32];
    float sum = warpSum(h0.x + h0.y + h0.z + h0.w + h1.x + h1.y + h1.z + h1.w);
    float mean = sum * (1.f / 256.f);
    h0.x -= mean; h0.y -= mean; h0.z -= mean; h0.w -= mean;
    h1.x -= mean; h1.y -= mean; h1.z -= mean; h1.w -= mean;
    float ss = warpSum(h0.x * h0.x + h0.y * h0.y + h0.z * h0.z + h0.w * h0.w
                     + h1.x * h1.x + h1.y * h1.y + h1.z * h1.z + h1.w * h1.w);
    float rstd = rsqrtf(ss * (1.f / 256.f) + 1e-5f);
    float4 cg0 = reinterpret_cast<const float4*>(cg)[lane];
    float4 cg1 = reinterpret_cast<const float4*>(cg)[lane + 32];
    float4 cb0 = reinterpret_cast<const float4*>(cbeta)[lane];
    float4 cb1 = reinterpret_cast<const float4*>(cbeta)[lane + 32];
    h0.x = fmaxf(h0.x * rstd * cg0.x + cb0.x, 0.f);
    h0.y = fmaxf(h0.y * rstd * cg0.y + cb0.y, 0.f);
    h0.z = fmaxf(h0.z * rstd * cg0.z + cb0.z, 0.f);
    h0.w = fmaxf(h0.w * rstd * cg0.w + cb0.w, 0.f);
    h1.x = fmaxf(h1.x * rstd * cg1.x + cb1.x, 0.f);
    h1.y = fmaxf(h1.y * rstd * cg1.y + cb1.y, 0.f);
    h1.z = fmaxf(h1.z * rstd * cg1.z + cb1.z, 0.f);
    h1.w = fmaxf(h1.w * rstd * cg1.w + cb1.w, 0.f);
#pragma unroll
    for (int c = 0; c < 6; c++) {
        const float4* wr = reinterpret_cast<const float4*>(cw2 + c * 256);
        float4 w0 = wr[lane], w1 = wr[lane + 32];
        float p = h0.x * w0.x + h0.y * w0.y + h0.z * w0.z + h0.w * w0.w
                + h1.x * w1.x + h1.y * w1.y + h1.z * w1.z + h1.w * w1.w;
        p = warpSum(p);
        if (lane == 0) logits[(size_t)b * 6 + c] = p + cb2[c];
    }
}

// ---------------------------------------------------------------------------
extern "C" void kernel_launch(void* const* d_in, const int* in_sizes, int n_in,
                              void* d_out, int out_size)
{
    const float* rgb       = (const float*)d_in[0];
    const float* pose      = (const float*)d_in[1];
    const float* flow      = (const float*)d_in[2];
    const float* rgb_w     = (const float*)d_in[3];
    const float* rgb_b     = (const float*)d_in[4];
    const float* rgb_g     = (const float*)d_in[5];
    const float* rgb_beta  = (const float*)d_in[6];
    const float* pose_w    = (const float*)d_in[7];
    const float* pose_b    = (const float*)d_in[8];
    const float* pose_g    = (const float*)d_in[9];
    const float* pose_beta = (const float*)d_in[10];
    const float* flow_w    = (const float*)d_in[11];
    const float* flow_b    = (const float*)d_in[12];
    const float* flow_g    = (const float*)d_in[13];
    const float* flow_beta = (const float*)d_in[14];
    const float* in_w      = (const float*)d_in[15];
    const float* in_b      = (const float*)d_in[16];
    const float* out_w     = (const float*)d_in[17];
    const float* out_b     = (const float*)d_in[18];
    const float* gw1       = (const float*)d_in[19];
    const float* gb1       = (const float*)d_in[20];
    const float* gw2       = (const float*)d_in[21];
    const float* gb2       = (const float*)d_in[22];
    const float* cw1       = (const float*)d_in[23];
    const float* cb1       = (const float*)d_in[24];
    const float* cg        = (const float*)d_in[25];
    const float* cbeta     = (const float*)d_in[26];
    const float* cw2       = (const float*)d_in[27];
    const float* cb2       = (const float*)d_in[28];

    float* out = (float*)d_out;                 // [B*6 logits | B*3 gate]
    float* logits_out = out;
    float* gate_out   = out + (size_t)BATCH * 6;

    float *proj, *qkv, *ctx, *att, *gh, *fused, *chid;
    cudaGetSymbolAddress((void**)&proj,  g_proj);
    cudaGetSymbolAddress((void**)&qkv,   g_qkv);
    cudaGetSymbolAddress((void**)&ctx,   g_ctx);
    cudaGetSymbolAddress((void**)&att,   g_att);
    cudaGetSymbolAddress((void**)&gh,    g_gh);
    cudaGetSymbolAddress((void**)&fused, g_fused);
    cudaGetSymbolAddress((void**)&chid,  g_chid);

    cudaFuncSetAttribute(gemm_tc<0>,
        cudaFuncAttributeMaxDynamicSharedMemorySize, T_SMEM);
    cudaFuncSetAttribute(gemm_tc<1>,
        cudaFuncAttributeMaxDynamicSharedMemorySize, T_SMEM);

    // 1) per-modality projections -> stacked/concat buffer (B,3,512)
    gemm_tc<0><<<dim3(4, 128), 256, T_SMEM>>>(rgb,  rgb_w,  rgb_b,  proj + 0,    768,  1536);
    gemm_tc<0><<<dim3(4, 128), 256, T_SMEM>>>(pose, pose_w, pose_b, proj + 512,  640,  1536);
    gemm_tc<0><<<dim3(4, 128), 256, T_SMEM>>>(flow, flow_w, flow_b, proj + 1024, 1024, 1536);
    // 2) LN + ReLU per (b, modality) row
    ln_relu3<<<BATCH * 3, 128>>>(proj, rgb_g, rgb_beta, pose_g, pose_beta,
                                 flow_g, flow_beta);
    // 3) packed QKV projection (49152 x 512) x (1536 x 512)^T
    gemm_tc<0><<<dim3(12, 384), 256, T_SMEM>>>(proj, in_w, in_b, qkv, 512, 1536);
    // 4) 3-token 8-head attention
    attn3<<<BATCH * 8 / 4, 128>>>(qkv, ctx);
    // 5) attention out-projection
    gemm_tc<0><<<dim3(4, 384), 256, T_SMEM>>>(ctx, out_w, out_b, att, 512, 512);
    // 6) gate MLP layer 1 (uses proj as (B,1536) concat) with ReLU
    gemm_tc<1><<<dim3(4, 128), 256, T_SMEM>>>(proj, gw1, gb1, gh, 1536, 512);
    // 7) gate logits + softmax + weighted fusion (also writes gate output)
    gate_fuse<<<BATCH, 128>>>(gh, gw2, gb2, att, fused, gate_out);
    // 8) classifier layer 1
    gemm_tc<0><<<dim3(2, 128), 256, T_SMEM>>>(fused, cw1, cb1, chid, 512, 256);
    // 9) LN + ReLU + 6-way head
    cls_head<<<BATCH / 4, 128>>>(chid, cg, cbeta, cw2, cb2, logits_out);
}

// round 5
// speedup vs baseline: 5.3358x; 2.0392x over previous
#include <cuda_runtime.h>
#include <cuda_fp16.h>
#include <cstdint>
#include <math.h>

// ---------------------------------------------------------------------------
// AttentionFusion on GB300 (sm_103): fp16 mma.sync (m16n8k16) GEMMs via
// ldmatrix, fp16 activation chain, fused elementwise kernels.
// B=16384, E=512, H=8, HD=64, NC=6.
// ---------------------------------------------------------------------------

#define BATCH 16384

// fp16 scratch
__device__ __half g_rgb_h [BATCH * 768];
__device__ __half g_pose_h[BATCH * 640];
__device__ __half g_flow_h[BATCH * 1024];
__device__ __half g_proj_h[BATCH * 1536];   // (B,3,512), post-LN in-place
__device__ __half g_qkv_h [BATCH * 4608];   // (B*3, 1536) rows
__device__ __half g_ctx_h [BATCH * 1536];
__device__ __half g_fused_h[BATCH * 512];
// fp16 weights
__device__ __half g_rgbw_h [512 * 768];
__device__ __half g_posew_h[512 * 640];
__device__ __half g_floww_h[512 * 1024];
__device__ __half g_inw_h  [1536 * 512];
__device__ __half g_outw_h [512 * 512];
__device__ __half g_gw1_h  [512 * 1536];
__device__ __half g_cw1_h  [256 * 512];
// fp32 scratch
__device__ float g_att [BATCH * 1536];
__device__ float g_gh  [BATCH * 512];
__device__ float g_chid[BATCH * 256];

__device__ __forceinline__ uint32_t smem_u32(const void* p) {
    uint32_t a;
    asm("{ .reg .u64 t; cvta.to.shared.u64 t, %1; cvt.u32.u64 %0, t; }"
        : "=r"(a) : "l"(p));
    return a;
}

// ---------------------------------------------------------------------------
// fp32 -> fp16 convert (n % 8 == 0)
// ---------------------------------------------------------------------------
__global__ void __launch_bounds__(256) f2h(
    const float* __restrict__ in, __half* __restrict__ out, int n)
{
    int i = (blockIdx.x * 256 + threadIdx.x) * 8;
    if (i >= n) return;
    float4 v0 = *reinterpret_cast<const float4*>(in + i);
    float4 v1 = *reinterpret_cast<const float4*>(in + i + 4);
    union { uint4 u; __half2 h[4]; } pk;
    pk.h[0] = __floats2half2_rn(v0.x, v0.y);
    pk.h[1] = __floats2half2_rn(v0.z, v0.w);
    pk.h[2] = __floats2half2_rn(v1.x, v1.y);
    pk.h[3] = __floats2half2_rn(v1.z, v1.w);
    *reinterpret_cast<uint4*>(out + i) = pk.u;
}

// ---------------------------------------------------------------------------
// fp16 tensor-core GEMM: C[M,N] = A[M,K] * W[N,K]^T + bias (torch Linear)
// BM=BN=128, BK=64 halves, 256 threads = 8 warps (4m x 2n), warp tile 32x64.
// 3-stage cp.async pipeline, SW128-swizzled smem, ldmatrix.x4 fragments,
// mma.m16n8k16.f16 with f32 accumulation.  Output fp16 or fp32.
// Requires M%128==0, N%128==0, K%64==0, K>=192.
// ---------------------------------------------------------------------------
constexpr int H_STAGEB = 32768;               // bytes per stage (A 16K + B 16K)
constexpr int H_SMEM   = 3 * H_STAGEB;        // 98304

__device__ __forceinline__ void storePair(float v0, float v1, __half* p) {
    *reinterpret_cast<__half2*>(p) = __floats2half2_rn(v0, v1);
}
__device__ __forceinline__ void storePair(float v0, float v1, float* p) {
    *reinterpret_cast<float2*>(p) = make_float2(v0, v1);
}

template<int RELU, typename OT>
__global__ void __launch_bounds__(256, 2) gemm_h(
    const __half* __restrict__ A, const __half* __restrict__ W,
    const float* __restrict__ bias, OT* __restrict__ C,
    int K, int ldc)
{
    extern __shared__ __align__(16) char smem[];
    const uint32_t sb = smem_u32(smem);
    const int tid = threadIdx.x;
    const int wid = tid >> 5, lane = tid & 31;
    const int q  = lane >> 2, kr = lane & 3;
    const int wm = wid & 3,  wn = wid >> 2;
    const int bm = blockIdx.y * 128, bn = blockIdx.x * 128;

    // cp.async: thread covers 64B (4 x 16B segs) of one 128B row, A and B
    const int lrow = tid >> 1;
    const int hoff = (tid & 1) * 32;               // halves
    const __half* Arow = A + (size_t)(bm + lrow) * K + hoff;
    const __half* Wrow = W + (size_t)(bn + lrow) * K + hoff;
    uint32_t dstA[4];
    {
        const uint32_t rowb = (uint32_t)lrow * 128;
        const uint32_t m = (lrow & 7) << 4;
#pragma unroll
        for (int i = 0; i < 4; i++) {
            const uint32_t seg = (tid & 1) * 4 + i;
            dstA[i] = sb + rowb + ((seg * 16) ^ m);
        }
    }

#define LOAD_CHUNK(kc_) do {                                                  \
        const uint32_t st_ = ((kc_) % 3) * H_STAGEB;                          \
        const __half* ap_ = Arow + (size_t)(kc_) * 64;                        \
        const __half* wp_ = Wrow + (size_t)(kc_) * 64;                        \
        _Pragma("unroll")                                                     \
        for (int i = 0; i < 4; i++)                                           \
            asm volatile("cp.async.cg.shared.global [%0], [%1], 16;"          \
                :: "r"(dstA[i] + st_), "l"(ap_ + i * 8) : "memory");          \
        _Pragma("unroll")                                                     \
        for (int i = 0; i < 4; i++)                                           \
            asm volatile("cp.async.cg.shared.global [%0], [%1], 16;"          \
                :: "r"(dstA[i] + st_ + 16384), "l"(wp_ + i * 8) : "memory");  \
        asm volatile("cp.async.commit_group;" ::: "memory");                  \
    } while (0)

    const int KC = K >> 6;
    LOAD_CHUNK(0); LOAD_CHUNK(1); LOAD_CHUNK(2);

    // ldmatrix address components (per thread)
    uint32_t rowbA[2], mAr[2], rowbB[4], mBr[4];
    const uint32_t colA0 = (lane >> 4) * 16;             // bytes
    const uint32_t colB0 = ((lane >> 3) & 1) * 16;       // bytes
#pragma unroll
    for (int t = 0; t < 2; t++) {
        const uint32_t r = wm * 32 + t * 16 + (lane & 15);
        rowbA[t] = r * 128; mAr[t] = (r & 7) << 4;
    }
#pragma unroll
    for (int jj = 0; jj < 4; jj++) {
        const uint32_t r = wn * 64 + jj * 16 + (lane & 7) + ((lane >> 4) & 1) * 8;
        rowbB[jj] = r * 128; mBr[jj] = (r & 7) << 4;
    }

    float c[2][8][4];
#pragma unroll
    for (int t = 0; t < 2; t++)
#pragma unroll
        for (int j = 0; j < 8; j++)
#pragma unroll
            for (int r = 0; r < 4; r++) c[t][j][r] = 0.f;

    for (int kc = 0; kc < KC; kc++) {
        asm volatile("cp.async.wait_group 2;" ::: "memory");
        __syncthreads();
        const uint32_t As = sb + (kc % 3) * H_STAGEB;
        const uint32_t Bs = As + 16384;
#pragma unroll
        for (int ks = 0; ks < 4; ks++) {
            uint32_t a[2][4], b[4][4];
#pragma unroll
            for (int t = 0; t < 2; t++) {
                const uint32_t ad = As + rowbA[t] + ((colA0 + ks * 32) ^ mAr[t]);
                asm volatile(
                    "ldmatrix.sync.aligned.m8n8.x4.shared.b16 {%0,%1,%2,%3}, [%4];"
                    : "=r"(a[t][0]), "=r"(a[t][1]), "=r"(a[t][2]), "=r"(a[t][3])
                    : "r"(ad));
            }
#pragma unroll
            for (int jj = 0; jj < 4; jj++) {
                const uint32_t bd = Bs + rowbB[jj] + ((colB0 + ks * 32) ^ mBr[jj]);
                asm volatile(
                    "ldmatrix.sync.aligned.m8n8.x4.shared.b16 {%0,%1,%2,%3}, [%4];"
                    : "=r"(b[jj][0]), "=r"(b[jj][1]), "=r"(b[jj][2]), "=r"(b[jj][3])
                    : "r"(bd));
            }
#pragma unroll
            for (int t = 0; t < 2; t++)
#pragma unroll
                for (int j = 0; j < 8; j++) {
                    const int jj = j >> 1, lo = (j & 1) * 2;
                    asm volatile(
                        "mma.sync.aligned.m16n8k16.row.col.f32.f16.f16.f32 "
                        "{%0,%1,%2,%3}, {%4,%5,%6,%7}, {%8,%9}, {%0,%1,%2,%3};"
                        : "+f"(c[t][j][0]), "+f"(c[t][j][1]),
                          "+f"(c[t][j][2]), "+f"(c[t][j][3])
                        : "r"(a[t][0]), "r"(a[t][1]), "r"(a[t][2]), "r"(a[t][3]),
                          "r"(b[jj][lo]), "r"(b[jj][lo + 1]));
                }
        }
        __syncthreads();
        const int kn = kc + 3;
        if (kn < KC) { LOAD_CHUNK(kn); }
        else asm volatile("cp.async.commit_group;" ::: "memory");
    }
#undef LOAD_CHUNK

    // epilogue: bias (+ReLU)
#pragma unroll
    for (int t = 0; t < 2; t++) {
        const int r0 = bm + wm * 32 + t * 16 + q;
#pragma unroll
        for (int j = 0; j < 8; j++) {
            const int col = bn + wn * 64 + j * 8 + (kr << 1);
            const float b0 = bias[col], b1 = bias[col + 1];
            float v00 = c[t][j][0] + b0, v01 = c[t][j][1] + b1;
            float v10 = c[t][j][2] + b0, v11 = c[t][j][3] + b1;
            if (RELU) {
                v00 = fmaxf(v00, 0.f); v01 = fmaxf(v01, 0.f);
                v10 = fmaxf(v10, 0.f); v11 = fmaxf(v11, 0.f);
            }
            storePair(v00, v01, C + (size_t)r0 * ldc + col);
            storePair(v10, v11, C + (size_t)(r0 + 8) * ldc + col);
        }
    }
}

// ---------------------------------------------------------------------------
// elementwise / small kernels
// ---------------------------------------------------------------------------
__device__ __forceinline__ float warpSum(float v) {
#pragma unroll
    for (int o = 16; o > 0; o >>= 1) v += __shfl_xor_sync(0xffffffffu, v, o);
    return v;
}

__device__ __forceinline__ float blockSum128(float v, float* sred) {
    int lane = threadIdx.x & 31, w = threadIdx.x >> 5;
    v = warpSum(v);
    __syncthreads();
    if (lane == 0) sred[w] = v;
    __syncthreads();
    return sred[0] + sred[1] + sred[2] + sred[3];
}

// in-place LN+ReLU on fp16 rows of 512; modality = row % 3
__global__ void __launch_bounds__(128) ln_relu3_h(
    __half* __restrict__ x,
    const float* __restrict__ g0, const float* __restrict__ be0,
    const float* __restrict__ g1, const float* __restrict__ be1,
    const float* __restrict__ g2, const float* __restrict__ be2)
{
    __shared__ float sred[4];
    int row = blockIdx.x;
    int s = row % 3;
    const float* g  = (s == 0) ? g0 : (s == 1) ? g1 : g2;
    const float* be = (s == 0) ? be0 : (s == 1) ? be1 : be2;
    __half* xr = x + (size_t)row * 512;
    int t = threadIdx.x;
    union { uint2 u; __half2 h[2]; } pk;
    pk.u = *reinterpret_cast<const uint2*>(xr + 4 * t);
    float2 f0 = __half22float2(pk.h[0]), f1 = __half22float2(pk.h[1]);
    float sum = blockSum128(f0.x + f0.y + f1.x + f1.y, sred);
    float mean = sum * (1.f / 512.f);
    float dx = f0.x - mean, dy = f0.y - mean, dz = f1.x - mean, dw = f1.y - mean;
    float ss = blockSum128(dx * dx + dy * dy + dz * dz + dw * dw, sred);
    float rstd = rsqrtf(ss * (1.f / 512.f) + 1e-5f);
    float4 gv = reinterpret_cast<const float4*>(g)[t];
    float4 bv = reinterpret_cast<const float4*>(be)[t];
    float ox = fmaxf(dx * rstd * gv.x + bv.x, 0.f);
    float oy = fmaxf(dy * rstd * gv.y + bv.y, 0.f);
    float oz = fmaxf(dz * rstd * gv.z + bv.z, 0.f);
    float ow = fmaxf(dw * rstd * gv.w + bv.w, 0.f);
    pk.h[0] = __floats2half2_rn(ox, oy);
    pk.h[1] = __floats2half2_rn(oz, ow);
    *reinterpret_cast<uint2*>(xr + 4 * t) = pk.u;
}

// 3-token, 8-head attention on fp16 qkv; one warp per (sample, head)
__global__ void __launch_bounds__(128) attn3_h(
    const __half* __restrict__ qkv, __half* __restrict__ ctx)
{
    int warp = blockIdx.x * 4 + (threadIdx.x >> 5);
    int lane = threadIdx.x & 31;
    int b = warp >> 3, h = warp & 7;
    const __half* base = qkv + (size_t)b * 4608 + h * 64 + 2 * lane;
    float2 q[3], k[3], v[3];
#pragma unroll
    for (int t = 0; t < 3; t++) {
        q[t] = __half22float2(*reinterpret_cast<const __half2*>(base + t * 1536));
        k[t] = __half22float2(*reinterpret_cast<const __half2*>(base + t * 1536 + 512));
        v[t] = __half22float2(*reinterpret_cast<const __half2*>(base + t * 1536 + 1024));
    }
    float a[3][3];
#pragma unroll
    for (int i = 0; i < 3; i++)
#pragma unroll
        for (int j = 0; j < 3; j++) {
            float p = q[i].x * k[j].x + q[i].y * k[j].y;
            a[i][j] = warpSum(p) * 0.125f;
        }
#pragma unroll
    for (int i = 0; i < 3; i++) {
        float m = fmaxf(a[i][0], fmaxf(a[i][1], a[i][2]));
        float e0 = expf(a[i][0] - m), e1 = expf(a[i][1] - m), e2 = expf(a[i][2] - m);
        float inv = 1.f / (e0 + e1 + e2);
        a[i][0] = e0 * inv; a[i][1] = e1 * inv; a[i][2] = e2 * inv;
    }
#pragma unroll
    for (int i = 0; i < 3; i++) {
        float ox = a[i][0] * v[0].x + a[i][1] * v[1].x + a[i][2] * v[2].x;
        float oy = a[i][0] * v[0].y + a[i][1] * v[1].y + a[i][2] * v[2].y;
        *reinterpret_cast<__half2*>(ctx + (size_t)(b * 3 + i) * 512 + h * 64 + 2 * lane)
            = __floats2half2_rn(ox, oy);
    }
}

// gate logits + softmax + weighted fuse; writes fp16 fused + fp32 gate
__global__ void __launch_bounds__(128) gate_fuse(
    const float* __restrict__ gh, const float* __restrict__ gw2,
    const float* __restrict__ gb2, const float* __restrict__ att,
    __half* __restrict__ fused, float* __restrict__ gate_out)
{
    __shared__ float sred[4];
    int b = blockIdx.x, t = threadIdx.x;
    float4 hv = reinterpret_cast<const float4*>(gh + (size_t)b * 512)[t];
    float l[3];
#pragma unroll
    for (int s = 0; s < 3; s++) {
        float4 w = reinterpret_cast<const float4*>(gw2 + s * 512)[t];
        l[s] = blockSum128(hv.x * w.x + hv.y * w.y + hv.z * w.z + hv.w * w.w, sred)
             + gb2[s];
    }
    float m = fmaxf(l[0], fmaxf(l[1], l[2]));
    float e0 = expf(l[0] - m), e1 = expf(l[1] - m), e2 = expf(l[2] - m);
    float inv = 1.f / (e0 + e1 + e2);
    float w0 = e0 * inv, w1 = e1 * inv, w2 = e2 * inv;
    if (t == 0) {
        gate_out[b * 3 + 0] = w0;
        gate_out[b * 3 + 1] = w1;
        gate_out[b * 3 + 2] = w2;
    }
    const float4* ar = reinterpret_cast<const float4*>(att + (size_t)b * 1536);
    float4 x0 = ar[t], x1 = ar[128 + t], x2 = ar[256 + t];
    union { uint2 u; __half2 h[2]; } pk;
    pk.h[0] = __floats2half2_rn(w0 * x0.x + w1 * x1.x + w2 * x2.x,
                                w0 * x0.y + w1 * x1.y + w2 * x2.y);
    pk.h[1] = __floats2half2_rn(w0 * x0.z + w1 * x1.z + w2 * x2.z,
                                w0 * x0.w + w1 * x1.w + w2 * x2.w);
    *reinterpret_cast<uint2*>(fused + (size_t)b * 512 + 4 * t) = pk.u;
}

// classifier head: LN(256) + ReLU + 6-way linear; one warp per sample
__global__ void __launch_bounds__(128) cls_head(
    const float* __restrict__ chid, const float* __restrict__ cg,
    const float* __restrict__ cbeta, const float* __restrict__ cw2,
    const float* __restrict__ cb2, float* __restrict__ logits)
{
    int b = blockIdx.x * 4 + (threadIdx.x >> 5);
    int lane = threadIdx.x & 31;
    const float* hr = chid + (size_t)b * 256;
    float4 h0 = reinterpret_cast<const float4*>(hr)[lane];
    float4 h1 = reinterpret_cast<const float4*>(hr)[lane + 32];
    float sum = warpSum(h0.x + h0.y + h0.z + h0.w + h1.x + h1.y + h1.z + h1.w);
    float mean = sum * (1.f / 256.f);
    h0.x -= mean; h0.y -= mean; h0.z -= mean; h0.w -= mean;
    h1.x -= mean; h1.y -= mean; h1.z -= mean; h1.w -= mean;
    float ss = warpSum(h0.x * h0.x + h0.y * h0.y + h0.z * h0.z + h0.w * h0.w
                     + h1.x * h1.x + h1.y * h1.y + h1.z * h1.z + h1.w * h1.w);
    float rstd = rsqrtf(ss * (1.f / 256.f) + 1e-5f);
    float4 cg0 = reinterpret_cast<const float4*>(cg)[lane];
    float4 cg1 = reinterpret_cast<const float4*>(cg)[lane + 32];
    float4 cb0 = reinterpret_cast<const float4*>(cbeta)[lane];
    float4 cb1 = reinterpret_cast<const float4*>(cbeta)[lane + 32];
    h0.x = fmaxf(h0.x * rstd * cg0.x + cb0.x, 0.f);
    h0.y = fmaxf(h0.y * rstd * cg0.y + cb0.y, 0.f);
    h0.z = fmaxf(h0.z * rstd * cg0.z + cb0.z, 0.f);
    h0.w = fmaxf(h0.w * rstd * cg0.w + cb0.w, 0.f);
    h1.x = fmaxf(h1.x * rstd * cg1.x + cb1.x, 0.f);
    h1.y = fmaxf(h1.y * rstd * cg1.y + cb1.y, 0.f);
    h1.z = fmaxf(h1.z * rstd * cg1.z + cb1.z, 0.f);
    h1.w = fmaxf(h1.w * rstd * cg1.w + cb1.w, 0.f);
#pragma unroll
    for (int c = 0; c < 6; c++) {
        const float4* wr = reinterpret_cast<const float4*>(cw2 + c * 256);
        float4 w0 = wr[lane], w1 = wr[lane + 32];
        float p = h0.x * w0.x + h0.y * w0.y + h0.z * w0.z + h0.w * w0.w
                + h1.x * w1.x + h1.y * w1.y + h1.z * w1.z + h1.w * w1.w;
        p = warpSum(p);
        if (lane == 0) logits[(size_t)b * 6 + c] = p + cb2[c];
    }
}

// ---------------------------------------------------------------------------
extern "C" void kernel_launch(void* const* d_in, const int* in_sizes, int n_in,
                              void* d_out, int out_size)
{
    const float* rgb       = (const float*)d_in[0];
    const float* pose      = (const float*)d_in[1];
    const float* flow      = (const float*)d_in[2];
    const float* rgb_w     = (const float*)d_in[3];
    const float* rgb_b     = (const float*)d_in[4];
    const float* rgb_g     = (const float*)d_in[5];
    const float* rgb_beta  = (const float*)d_in[6];
    const float* pose_w    = (const float*)d_in[7];
    const float* pose_b    = (const float*)d_in[8];
    const float* pose_g    = (const float*)d_in[9];
    const float* pose_beta = (const float*)d_in[10];
    const float* flow_w    = (const float*)d_in[11];
    const float* flow_b    = (const float*)d_in[12];
    const float* flow_g    = (const float*)d_in[13];
    const float* flow_beta = (const float*)d_in[14];
    const float* in_w      = (const float*)d_in[15];
    const float* in_b      = (const float*)d_in[16];
    const float* out_w     = (const float*)d_in[17];
    const float* out_b     = (const float*)d_in[18];
    const float* gw1       = (const float*)d_in[19];
    const float* gb1       = (const float*)d_in[20];
    const float* gw2       = (const float*)d_in[21];
    const float* gb2       = (const float*)d_in[22];
    const float* cw1       = (const float*)d_in[23];
    const float* cb1       = (const float*)d_in[24];
    const float* cg        = (const float*)d_in[25];
    const float* cbeta     = (const float*)d_in[26];
    const float* cw2       = (const float*)d_in[27];
    const float* cb2       = (const float*)d_in[28];

    float* out = (float*)d_out;                 // [B*6 logits | B*3 gate]
    float* logits_out = out;
    float* gate_out   = out + (size_t)BATCH * 6;

    __half *rgb_h, *pose_h, *flow_h, *proj_h, *qkv_h, *ctx_h, *fused_h;
    __half *rgbw_h, *posew_h, *floww_h, *inw_h, *outw_h, *gw1_h, *cw1_h;
    float *att, *gh, *chid;
    cudaGetSymbolAddress((void**)&rgb_h,   g_rgb_h);
    cudaGetSymbolAddress((void**)&pose_h,  g_pose_h);
    cudaGetSymbolAddress((void**)&flow_h,  g_flow_h);
    cudaGetSymbolAddress((void**)&proj_h,  g_proj_h);
    cudaGetSymbolAddress((void**)&qkv_h,   g_qkv_h);
    cudaGetSymbolAddress((void**)&ctx_h,   g_ctx_h);
    cudaGetSymbolAddress((void**)&fused_h, g_fused_h);
    cudaGetSymbolAddress((void**)&rgbw_h,  g_rgbw_h);
    cudaGetSymbolAddress((void**)&posew_h, g_posew_h);
    cudaGetSymbolAddress((void**)&floww_h, g_floww_h);
    cudaGetSymbolAddress((void**)&inw_h,   g_inw_h);
    cudaGetSymbolAddress((void**)&outw_h,  g_outw_h);
    cudaGetSymbolAddress((void**)&gw1_h,   g_gw1_h);
    cudaGetSymbolAddress((void**)&cw1_h,   g_cw1_h);
    cudaGetSymbolAddress((void**)&att,  g_att);
    cudaGetSymbolAddress((void**)&gh,   g_gh);
    cudaGetSymbolAddress((void**)&chid, g_chid);

    cudaFuncSetAttribute((const void*)gemm_h<0, __half>,
        cudaFuncAttributeMaxDynamicSharedMemorySize, H_SMEM);
    cudaFuncSetAttribute((const void*)gemm_h<0, float>,
        cudaFuncAttributeMaxDynamicSharedMemorySize, H_SMEM);
    cudaFuncSetAttribute((const void*)gemm_h<1, float>,
        cudaFuncAttributeMaxDynamicSharedMemorySize, H_SMEM);

    // 0) fp32 -> fp16 conversions (inputs + GEMM weights)
    auto cvt = [](const float* src, __half* dst, int n) {
        f2h<<<(n / 8 + 255) / 256, 256>>>(src, dst, n);
    };
    cvt(rgb,    rgb_h,   BATCH * 768);
    cvt(pose,   pose_h,  BATCH * 640);
    cvt(flow,   flow_h,  BATCH * 1024);
    cvt(rgb_w,  rgbw_h,  512 * 768);
    cvt(pose_w, posew_h, 512 * 640);
    cvt(flow_w, floww_h, 512 * 1024);
    cvt(in_w,   inw_h,   1536 * 512);
    cvt(out_w,  outw_h,  512 * 512);
    cvt(gw1,    gw1_h,   512 * 1536);
    cvt(cw1,    cw1_h,   256 * 512);

    // 1) per-modality projections -> stacked/concat fp16 buffer (B,3,512)
    gemm_h<0, __half><<<dim3(4, 128), 256, H_SMEM>>>(rgb_h,  rgbw_h,  rgb_b,  proj_h + 0,    768,  1536);
    gemm_h<0, __half><<<dim3(4, 128), 256, H_SMEM>>>(pose_h, posew_h, pose_b, proj_h + 512,  640,  1536);
    gemm_h<0, __half><<<dim3(4, 128), 256, H_SMEM>>>(flow_h, floww_h, flow_b, proj_h + 1024, 1024, 1536);
    // 2) LN + ReLU per (b, modality) row (in-place fp16)
    ln_relu3_h<<<BATCH * 3, 128>>>(proj_h, rgb_g, rgb_beta, pose_g, pose_beta,
                                   flow_g, flow_beta);
    // 3) packed QKV projection: (49152 x 512) x (1536 x 512)^T -> (49152,1536)
    gemm_h<0, __half><<<dim3(12, 384), 256, H_SMEM>>>(proj_h, inw_h, in_b, qkv_h, 512, 1536);
    // 4) 3-token 8-head attention -> fp16 ctx
    attn3_h<<<BATCH * 8 / 4, 128>>>(qkv_h, ctx_h);
    // 5) attention out-projection -> fp32 att
    gemm_h<0, float><<<dim3(4, 384), 256, H_SMEM>>>(ctx_h, outw_h, out_b, att, 512, 512);
    // 6) gate MLP layer 1 (proj_h as (B,1536) concat) + ReLU -> fp32 gh
    gemm_h<1, float><<<dim3(4, 128), 256, H_SMEM>>>(proj_h, gw1_h, gb1, gh, 1536, 512);
    // 7) gate logits + softmax + weighted fusion -> fp16 fused + gate out
    gate_fuse<<<BATCH, 128>>>(gh, gw2, gb2, att, fused_h, gate_out);
    // 8) classifier layer 1 -> fp32 chid
    gemm_h<0, float><<<dim3(2, 128), 256, H_SMEM>>>(fused_h, cw1_h, cb1, chid, 512, 256);
    // 9) LN + ReLU + 6-way head
    cls_head<<<BATCH / 4, 128>>>(chid, cg, cbeta, cw2, cb2, logits_out);
}